// round 1
// baseline (speedup 1.0000x reference)
#include <cuda_runtime.h>
#include <cstdint>

#define B_      8
#define AT_     96
#define NBR_    512
#define NANG_   125
#define NF_     128
#define NB_     128
#define ATOMS_  (B_*AT_)      // 768
#define CHUNK_  64
#define NCHUNK_ (NBR_/CHUNK_) // 8
#define PITCH_  132           // 132 mod 32 == 4 -> conflict-free fragment LDS

// shared memory layout (u32 units)
#define SM_W1   0
#define SM_W2   (128*PITCH_)
#define SM_T    (2*128*PITCH_)
#define SM_H    (SM_T + CHUNK_*PITCH_)
#define SM_F    (SM_H + CHUNK_*PITCH_)
// float extras after SM_F: b1s[128], b2s[128], js[64], ks[64], ms[64], aggs[256], t1s[128]
#define SMEM_U32   (SM_F + 128+128+64+64+64+256+128)
#define SMEM_BYTES (SMEM_U32*4)   // 206080 bytes

__device__ float g_y[ATOMS_ * NF_];   // scratch: y = x @ Win

__device__ __forceinline__ uint32_t f2tf32(float x) {
    uint32_t u; asm("cvt.rna.tf32.f32 %0, %1;" : "=r"(u) : "f"(x)); return u;
}

__device__ __forceinline__ float sspf(float x) {
    // softplus(x) - ln2, numerically stable
    return fmaxf(x, 0.f) + __logf(1.f + __expf(-fabsf(x))) - 0.6931471805599453f;
}

__device__ __forceinline__ void mma_tf32(float c[4], const uint32_t a[4], const uint32_t b[2]) {
    asm volatile(
        "mma.sync.aligned.m16n8k8.row.col.f32.tf32.tf32.f32 "
        "{%0,%1,%2,%3}, {%4,%5,%6,%7}, {%8,%9}, {%0,%1,%2,%3};"
        : "+f"(c[0]), "+f"(c[1]), "+f"(c[2]), "+f"(c[3])
        : "r"(a[0]), "r"(a[1]), "r"(a[2]), "r"(a[3]), "r"(b[0]), "r"(b[1]));
}

// ---------------------------------------------------------------------------
// Kernel A: y = x @ Win   (768 rows, 128x128)
// ---------------------------------------------------------------------------
__global__ void __launch_bounds__(128)
y_kernel(const float* __restrict__ x, const float* __restrict__ Win)
{
    __shared__ float xs[NB_];
    const int row = blockIdx.x, t = threadIdx.x;
    xs[t] = x[row*NB_ + t];
    __syncthreads();
    float acc = 0.f;
    #pragma unroll 16
    for (int gg = 0; gg < NB_; ++gg)
        acc = fmaf(xs[gg], Win[gg*NF_ + t], acc);
    g_y[row*NF_ + t] = acc;
}

// ---------------------------------------------------------------------------
// Fused main kernel: one CTA per atom (b, a)
// ---------------------------------------------------------------------------
__global__ void __launch_bounds__(256, 1)
fused_kernel(const float* __restrict__ triple,
             const int*   __restrict__ nj, const int* __restrict__ nk,
             const float* __restrict__ mask,
             const float* __restrict__ W1, const float* __restrict__ b1,
             const float* __restrict__ W2, const float* __restrict__ b2,
             const float* __restrict__ Wf2, const float* __restrict__ bf2,
             const float* __restrict__ Wd,  const float* __restrict__ bd,
             const float* __restrict__ x,   float* __restrict__ out)
{
    extern __shared__ uint32_t sm[];
    uint32_t* W1s = sm + SM_W1;
    uint32_t* W2s = sm + SM_W2;
    uint32_t* Ts  = sm + SM_T;
    uint32_t* Hs  = sm + SM_H;
    float*    Tf  = reinterpret_cast<float*>(Ts);     // W_triple tile view (f32)
    float*    fx  = reinterpret_cast<float*>(sm + SM_F);
    float* b1s = fx;
    float* b2s = fx + 128;
    int*   js  = reinterpret_cast<int*>(fx + 256);
    int*   ks  = js + 64;
    float* ms  = fx + 256 + 128;          // after js(64)+ks(64)
    float* aggs = ms + 64;                // 256
    float* t1s  = aggs + 256;             // 128

    const int t    = threadIdx.x;
    const int atom = blockIdx.x;
    const int bidx = atom / AT_;
    const int lane = t & 31;
    const int warp = t >> 5;
    const int g  = lane >> 2;      // groupID
    const int c  = lane & 3;       // thread-in-group
    const int mg = warp >> 2;      // 0..1  (M 32-row group)
    const int ng = warp & 3;       // 0..3  (N 32-col group)

    // ---- stage W1 (125x128, tf32, pitch 132, zero-padded rows 125..127) ----
    for (int e4 = t; e4 < (NANG_*NF_)/4; e4 += 256) {
        float4 v = reinterpret_cast<const float4*>(W1)[e4];
        int e = e4 << 2;
        int r = e >> 7, cc = e & 127;          // NF_=128, row-aligned float4
        uint32_t* p = &W1s[r*PITCH_ + cc];
        p[0]=f2tf32(v.x); p[1]=f2tf32(v.y); p[2]=f2tf32(v.z); p[3]=f2tf32(v.w);
    }
    for (int e = t; e < 3*128; e += 256)
        W1s[(125 + (e>>7))*PITCH_ + (e & 127)] = 0u;
    // ---- stage W2 (128x128) ----
    for (int e4 = t; e4 < (NF_*NF_)/4; e4 += 256) {
        float4 v = reinterpret_cast<const float4*>(W2)[e4];
        int e = e4 << 2;
        int r = e >> 7, cc = e & 127;
        uint32_t* p = &W2s[r*PITCH_ + cc];
        p[0]=f2tf32(v.x); p[1]=f2tf32(v.y); p[2]=f2tf32(v.z); p[3]=f2tf32(v.w);
    }
    if (t < 128) { b1s[t] = b1[t]; b2s[t] = b2[t]; }

    const size_t tb = (size_t)atom * NBR_ * NANG_;
    const int    nb = atom * NBR_;

    // register prefetch of chunk 0 (64*125 floats = 2000 float4)
    float4 tr[8];
    {
        const float4* src = reinterpret_cast<const float4*>(triple + tb);
        #pragma unroll
        for (int i = 0; i < 8; ++i) { int idx = t + i*256; if (idx < 2000) tr[i] = src[idx]; }
    }

    float aggAcc = 0.f;
    const int f    = t & 127;
    const int half = t >> 7;
    const float* yb = g_y + bidx * AT_ * NF_;

    for (int ch = 0; ch < NCHUNK_; ++ch) {
        __syncthreads();   // previous chunk's elementwise done reading Tf

        // ---- store T tile as tf32 (handles row span: 125 % 4 != 0) ----
        #pragma unroll
        for (int i = 0; i < 8; ++i) {
            int idx = t + i*256;
            if (idx < 2000) {
                float v[4] = {tr[i].x, tr[i].y, tr[i].z, tr[i].w};
                #pragma unroll
                for (int jj = 0; jj < 4; ++jj) {
                    int e  = idx*4 + jj;
                    int r  = e / 125;
                    int cc = e - r*125;
                    Ts[r*PITCH_ + cc] = f2tf32(v[jj]);
                }
            }
        }
        if (t < 192) Ts[(t/3)*PITCH_ + 125 + (t%3)] = 0u;   // zero pad cols 125..127
        if (t < CHUNK_) {
            js[t] = nj[nb + ch*CHUNK_ + t];
            ks[t] = nk[nb + ch*CHUNK_ + t];
            ms[t] = mask[nb + ch*CHUNK_ + t];
        }
        // prefetch next chunk into registers (hidden behind GEMMs/elementwise)
        float4 tr2[8];
        if (ch + 1 < NCHUNK_) {
            const float4* src = reinterpret_cast<const float4*>(
                triple + tb + (size_t)(ch+1)*CHUNK_*NANG_);
            #pragma unroll
            for (int i = 0; i < 8; ++i) { int idx = t + i*256; if (idx < 2000) tr2[i] = src[idx]; }
        }
        __syncthreads();

        // ================= GEMM1: H = ssp(T @ W1 + b1) =================
        {
            float acc[2][4][4];
            #pragma unroll
            for (int mt=0;mt<2;mt++)
                #pragma unroll
                for (int nt=0;nt<4;nt++)
                    #pragma unroll
                    for (int i=0;i<4;i++) acc[mt][nt][i]=0.f;
            #pragma unroll
            for (int kk = 0; kk < 16; ++kk) {
                const int k0 = kk*8;
                uint32_t a[2][4], bb[4][2];
                #pragma unroll
                for (int mt = 0; mt < 2; ++mt) {
                    int r0 = mg*32 + mt*16 + g;
                    a[mt][0]=Ts[ r0   *PITCH_ + k0 + c    ];
                    a[mt][1]=Ts[(r0+8)*PITCH_ + k0 + c    ];
                    a[mt][2]=Ts[ r0   *PITCH_ + k0 + c + 4];
                    a[mt][3]=Ts[(r0+8)*PITCH_ + k0 + c + 4];
                }
                #pragma unroll
                for (int nt = 0; nt < 4; ++nt) {
                    int n0 = ng*32 + nt*8 + g;
                    bb[nt][0]=W1s[(k0+c  )*PITCH_ + n0];
                    bb[nt][1]=W1s[(k0+c+4)*PITCH_ + n0];
                }
                #pragma unroll
                for (int mt = 0; mt < 2; ++mt)
                    #pragma unroll
                    for (int nt = 0; nt < 4; ++nt)
                        mma_tf32(acc[mt][nt], a[mt], bb[nt]);
            }
            #pragma unroll
            for (int mt = 0; mt < 2; ++mt)
                #pragma unroll
                for (int nt = 0; nt < 4; ++nt)
                    #pragma unroll
                    for (int i = 0; i < 4; ++i) {
                        int row = mg*32 + mt*16 + g + ((i>>1)<<3);
                        int col = ng*32 + nt*8 + (c<<1) + (i&1);
                        float v = sspf(acc[mt][nt][i] + b1s[col]);
                        Hs[row*PITCH_ + col] = f2tf32(v);
                    }
        }
        __syncthreads();

        // ================= GEMM2: Wt = H @ W2 + b2  (-> Tf) =================
        {
            float acc[2][4][4];
            #pragma unroll
            for (int mt=0;mt<2;mt++)
                #pragma unroll
                for (int nt=0;nt<4;nt++)
                    #pragma unroll
                    for (int i=0;i<4;i++) acc[mt][nt][i]=0.f;
            #pragma unroll
            for (int kk = 0; kk < 16; ++kk) {
                const int k0 = kk*8;
                uint32_t a[2][4], bb[4][2];
                #pragma unroll
                for (int mt = 0; mt < 2; ++mt) {
                    int r0 = mg*32 + mt*16 + g;
                    a[mt][0]=Hs[ r0   *PITCH_ + k0 + c    ];
                    a[mt][1]=Hs[(r0+8)*PITCH_ + k0 + c    ];
                    a[mt][2]=Hs[ r0   *PITCH_ + k0 + c + 4];
                    a[mt][3]=Hs[(r0+8)*PITCH_ + k0 + c + 4];
                }
                #pragma unroll
                for (int nt = 0; nt < 4; ++nt) {
                    int n0 = ng*32 + nt*8 + g;
                    bb[nt][0]=W2s[(k0+c  )*PITCH_ + n0];
                    bb[nt][1]=W2s[(k0+c+4)*PITCH_ + n0];
                }
                #pragma unroll
                for (int mt = 0; mt < 2; ++mt)
                    #pragma unroll
                    for (int nt = 0; nt < 4; ++nt)
                        mma_tf32(acc[mt][nt], a[mt], bb[nt]);
            }
            #pragma unroll
            for (int mt = 0; mt < 2; ++mt)
                #pragma unroll
                for (int nt = 0; nt < 4; ++nt)
                    #pragma unroll
                    for (int i = 0; i < 4; ++i) {
                        int row = mg*32 + mt*16 + g + ((i>>1)<<3);
                        int col = ng*32 + nt*8 + (c<<1) + (i&1);
                        Tf[row*PITCH_ + col] = acc[mt][nt][i] + b2s[col];
                    }
        }
        __syncthreads();

        // ===== elementwise: agg[f] += mask * y_j[f] * y_k[f] * Wt[r][f] =====
        #pragma unroll 8
        for (int r = half; r < CHUNK_; r += 2) {
            int jrow = js[r], krow = ks[r];
            float m  = ms[r];
            float yj = yb[jrow*NF_ + f];
            float yk = yb[krow*NF_ + f];
            float wt = Tf[r*PITCH_ + f];
            aggAcc = fmaf(m * yj * yk, wt, aggAcc);
        }

        if (ch + 1 < NCHUNK_) {
            #pragma unroll
            for (int i = 0; i < 8; ++i) tr[i] = tr2[i];
        }
    }

    // ===== per-atom epilogue: v = ssp(agg@Wf2+bf2) @ Wd + bd; out = x + v =====
    aggs[half*128 + f] = aggAcc;
    __syncthreads();
    if (t < 128) aggs[t] = aggs[t] + aggs[128 + t];
    __syncthreads();
    if (t < 128) {
        float a1 = bf2[t];
        #pragma unroll 8
        for (int gg = 0; gg < 128; ++gg)
            a1 = fmaf(aggs[gg], Wf2[gg*NB_ + t], a1);
        t1s[t] = sspf(a1);
    }
    __syncthreads();
    if (t < 128) {
        float a2 = bd[t];
        #pragma unroll 8
        for (int gg = 0; gg < 128; ++gg)
            a2 = fmaf(t1s[gg], Wd[gg*NB_ + t], a2);
        out[atom*NB_ + t] = x[atom*NB_ + t] + a2;
    }
}

// ---------------------------------------------------------------------------
extern "C" void kernel_launch(void* const* d_in, const int* in_sizes, int n_in,
                              void* d_out, int out_size)
{
    const float* x      = (const float*)d_in[0];
    const float* triple = (const float*)d_in[1];
    const int*   nj     = (const int*)  d_in[2];
    const int*   nk     = (const int*)  d_in[3];
    const float* mask   = (const float*)d_in[4];
    const float* W1     = (const float*)d_in[5];
    const float* b1     = (const float*)d_in[6];
    const float* W2     = (const float*)d_in[7];
    const float* b2     = (const float*)d_in[8];
    const float* Win    = (const float*)d_in[9];
    const float* Wf2    = (const float*)d_in[10];
    const float* bf2    = (const float*)d_in[11];
    const float* Wd     = (const float*)d_in[12];
    const float* bd     = (const float*)d_in[13];
    float* out = (float*)d_out;

    cudaFuncSetAttribute(fused_kernel,
                         cudaFuncAttributeMaxDynamicSharedMemorySize, SMEM_BYTES);

    y_kernel<<<ATOMS_, 128>>>(x, Win);
    fused_kernel<<<ATOMS_, 256, SMEM_BYTES>>>(triple, nj, nk, mask,
                                              W1, b1, W2, b2,
                                              Wf2, bf2, Wd, bd, x, out);
}

// round 2
// speedup vs baseline: 1.1847x; 1.1847x over previous
#include <cuda_runtime.h>
#include <cstdint>

#define B_      8
#define AT_     96
#define NBR_    512
#define NANG_   125
#define NF_     128
#define NB_     128
#define ATOMS_  (B_*AT_)      // 768
#define CHUNK_  64
#define NCHUNK_ (NBR_/CHUNK_) // 8
#define PITCH_  132           // 132 mod 32 == 4 -> conflict-free fragment LDS

// shared memory layout (u32 units): only T and H tiles + small extras
#define SM_T    0
#define SM_H    (CHUNK_*PITCH_)
#define SM_F    (2*CHUNK_*PITCH_)
// float extras: b1s[128], b2s[128], js[64], ks[64], ms[64], aggs[256], t1s[128]
#define SMEM_U32   (SM_F + 128+128+64+64+64+256+128)
#define SMEM_BYTES (SMEM_U32*4)   // 70912 bytes -> 3 CTAs/SM

__device__ float    g_y[ATOMS_ * NF_];     // scratch: y = x @ Win
__device__ uint32_t g_W1t[128 * 128];      // W1 as tf32, zero-padded rows 125..127
__device__ uint32_t g_W2t[128 * 128];      // W2 as tf32

__device__ __forceinline__ uint32_t f2tf32(float x) {
    uint32_t u; asm("cvt.rna.tf32.f32 %0, %1;" : "=r"(u) : "f"(x)); return u;
}

__device__ __forceinline__ float sspf(float x) {
    return fmaxf(x, 0.f) + __logf(1.f + __expf(-fabsf(x))) - 0.6931471805599453f;
}

__device__ __forceinline__ void mma_tf32(float c[4], const uint32_t a[4], const uint32_t b[2]) {
    asm volatile(
        "mma.sync.aligned.m16n8k8.row.col.f32.tf32.tf32.f32 "
        "{%0,%1,%2,%3}, {%4,%5,%6,%7}, {%8,%9}, {%0,%1,%2,%3};"
        : "+f"(c[0]), "+f"(c[1]), "+f"(c[2]), "+f"(c[3])
        : "r"(a[0]), "r"(a[1]), "r"(a[2]), "r"(a[3]), "r"(b[0]), "r"(b[1]));
}

// ---------------------------------------------------------------------------
// Prep kernel A: y = x @ Win   (768 rows, 128x128)
// ---------------------------------------------------------------------------
__global__ void __launch_bounds__(128)
y_kernel(const float* __restrict__ x, const float* __restrict__ Win)
{
    __shared__ float xs[NB_];
    const int row = blockIdx.x, t = threadIdx.x;
    xs[t] = x[row*NB_ + t];
    __syncthreads();
    float acc = 0.f;
    #pragma unroll 16
    for (int gg = 0; gg < NB_; ++gg)
        acc = fmaf(xs[gg], Win[gg*NF_ + t], acc);
    g_y[row*NF_ + t] = acc;
}

// ---------------------------------------------------------------------------
// Prep kernel B: convert W1 (padded) and W2 to tf32 in global scratch
// ---------------------------------------------------------------------------
__global__ void __launch_bounds__(128)
wconv_kernel(const float* __restrict__ W1, const float* __restrict__ W2)
{
    const int r = blockIdx.x;           // 0..255
    const int t = threadIdx.x;          // 0..127
    if (r < 128) {
        g_W1t[r*128 + t] = (r < NANG_) ? f2tf32(W1[r*128 + t]) : 0u;
    } else {
        int rr = r - 128;
        g_W2t[rr*128 + t] = f2tf32(W2[rr*128 + t]);
    }
}

// ---------------------------------------------------------------------------
// Fused main kernel: one CTA per atom
// ---------------------------------------------------------------------------
__global__ void __launch_bounds__(256, 3)
fused_kernel(const float* __restrict__ triple,
             const int*   __restrict__ nj, const int* __restrict__ nk,
             const float* __restrict__ mask,
             const float* __restrict__ b1, const float* __restrict__ b2,
             const float* __restrict__ Wf2, const float* __restrict__ bf2,
             const float* __restrict__ Wd,  const float* __restrict__ bd,
             const float* __restrict__ x,   float* __restrict__ out)
{
    extern __shared__ uint32_t sm[];
    uint32_t* Ts  = sm + SM_T;
    uint32_t* Hs  = sm + SM_H;
    float*    Tf  = reinterpret_cast<float*>(Ts);     // GEMM2 output view (f32)
    float*    fx  = reinterpret_cast<float*>(sm + SM_F);
    float* b1s = fx;
    float* b2s = fx + 128;
    int*   js  = reinterpret_cast<int*>(fx + 256);
    int*   ks  = js + 64;
    float* ms  = fx + 256 + 128;
    float* aggs = ms + 64;                // 256
    float* t1s  = aggs + 256;             // 128

    const int t    = threadIdx.x;
    const int atom = blockIdx.x;
    const int bidx = atom / AT_;
    const int lane = t & 31;
    const int warp = t >> 5;
    const int g  = lane >> 2;      // groupID
    const int c  = lane & 3;       // thread-in-group
    const int mg = warp >> 2;      // 0..1  (M 32-row group)
    const int ng = warp & 3;       // 0..3  (N 32-col group)

    if (t < 128) { b1s[t] = b1[t]; b2s[t] = b2[t]; }

    const size_t tb = (size_t)atom * NBR_ * NANG_;
    const int    nb = atom * NBR_;

    float aggAcc = 0.f;
    const int f    = t & 127;
    const int half = t >> 7;
    const float* yb = g_y + bidx * AT_ * NF_;

    for (int ch = 0; ch < NCHUNK_; ++ch) {
        __syncthreads();   // previous chunk's elementwise done reading Tf

        // ---- load + store T tile as tf32 (64 x 125, pitch 132, pad to 128) ----
        {
            const float4* src = reinterpret_cast<const float4*>(
                triple + tb + (size_t)ch*CHUNK_*NANG_);
            #pragma unroll
            for (int i = 0; i < 8; ++i) {
                int idx = t + i*256;
                if (idx < 2000) {
                    float4 v4 = src[idx];
                    float v[4] = {v4.x, v4.y, v4.z, v4.w};
                    #pragma unroll
                    for (int jj = 0; jj < 4; ++jj) {
                        int e  = idx*4 + jj;
                        int r  = e / 125;
                        int cc = e - r*125;
                        Ts[r*PITCH_ + cc] = f2tf32(v[jj]);
                    }
                }
            }
        }
        if (t < 192) Ts[(t/3)*PITCH_ + 125 + (t%3)] = 0u;   // zero pad cols 125..127
        if (t < CHUNK_) {
            js[t] = nj[nb + ch*CHUNK_ + t];
            ks[t] = nk[nb + ch*CHUNK_ + t];
            ms[t] = mask[nb + ch*CHUNK_ + t];
        }
        __syncthreads();

        // ================= GEMM1: H = ssp(T @ W1 + b1) =================
        {
            float acc[2][4][4];
            #pragma unroll
            for (int mt=0;mt<2;mt++)
                #pragma unroll
                for (int nt=0;nt<4;nt++)
                    #pragma unroll
                    for (int i=0;i<4;i++) acc[mt][nt][i]=0.f;
            #pragma unroll
            for (int kk = 0; kk < 16; ++kk) {
                const int k0 = kk*8;
                uint32_t a[2][4], bb[4][2];
                #pragma unroll
                for (int mt = 0; mt < 2; ++mt) {
                    int r0 = mg*32 + mt*16 + g;
                    a[mt][0]=Ts[ r0   *PITCH_ + k0 + c    ];
                    a[mt][1]=Ts[(r0+8)*PITCH_ + k0 + c    ];
                    a[mt][2]=Ts[ r0   *PITCH_ + k0 + c + 4];
                    a[mt][3]=Ts[(r0+8)*PITCH_ + k0 + c + 4];
                }
                #pragma unroll
                for (int nt = 0; nt < 4; ++nt) {
                    int n0 = ng*32 + nt*8 + g;
                    bb[nt][0]=__ldg(&g_W1t[(k0+c  )*128 + n0]);
                    bb[nt][1]=__ldg(&g_W1t[(k0+c+4)*128 + n0]);
                }
                #pragma unroll
                for (int mt = 0; mt < 2; ++mt)
                    #pragma unroll
                    for (int nt = 0; nt < 4; ++nt)
                        mma_tf32(acc[mt][nt], a[mt], bb[nt]);
            }
            #pragma unroll
            for (int mt = 0; mt < 2; ++mt)
                #pragma unroll
                for (int nt = 0; nt < 4; ++nt)
                    #pragma unroll
                    for (int i = 0; i < 4; ++i) {
                        int row = mg*32 + mt*16 + g + ((i>>1)<<3);
                        int col = ng*32 + nt*8 + (c<<1) + (i&1);
                        float v = sspf(acc[mt][nt][i] + b1s[col]);
                        Hs[row*PITCH_ + col] = f2tf32(v);
                    }
        }
        __syncthreads();

        // ================= GEMM2: Wt = H @ W2 + b2  (-> Tf) =================
        {
            float acc[2][4][4];
            #pragma unroll
            for (int mt=0;mt<2;mt++)
                #pragma unroll
                for (int nt=0;nt<4;nt++)
                    #pragma unroll
                    for (int i=0;i<4;i++) acc[mt][nt][i]=0.f;
            #pragma unroll
            for (int kk = 0; kk < 16; ++kk) {
                const int k0 = kk*8;
                uint32_t a[2][4], bb[4][2];
                #pragma unroll
                for (int mt = 0; mt < 2; ++mt) {
                    int r0 = mg*32 + mt*16 + g;
                    a[mt][0]=Hs[ r0   *PITCH_ + k0 + c    ];
                    a[mt][1]=Hs[(r0+8)*PITCH_ + k0 + c    ];
                    a[mt][2]=Hs[ r0   *PITCH_ + k0 + c + 4];
                    a[mt][3]=Hs[(r0+8)*PITCH_ + k0 + c + 4];
                }
                #pragma unroll
                for (int nt = 0; nt < 4; ++nt) {
                    int n0 = ng*32 + nt*8 + g;
                    bb[nt][0]=__ldg(&g_W2t[(k0+c  )*128 + n0]);
                    bb[nt][1]=__ldg(&g_W2t[(k0+c+4)*128 + n0]);
                }
                #pragma unroll
                for (int mt = 0; mt < 2; ++mt)
                    #pragma unroll
                    for (int nt = 0; nt < 4; ++nt)
                        mma_tf32(acc[mt][nt], a[mt], bb[nt]);
            }
            #pragma unroll
            for (int mt = 0; mt < 2; ++mt)
                #pragma unroll
                for (int nt = 0; nt < 4; ++nt)
                    #pragma unroll
                    for (int i = 0; i < 4; ++i) {
                        int row = mg*32 + mt*16 + g + ((i>>1)<<3);
                        int col = ng*32 + nt*8 + (c<<1) + (i&1);
                        Tf[row*PITCH_ + col] = acc[mt][nt][i] + b2s[col];
                    }
        }
        __syncthreads();

        // ===== elementwise: agg[f] += mask * y_j[f] * y_k[f] * Wt[r][f] =====
        #pragma unroll 8
        for (int r = half; r < CHUNK_; r += 2) {
            int jrow = js[r], krow = ks[r];
            float m  = ms[r];
            float yj = yb[jrow*NF_ + f];
            float yk = yb[krow*NF_ + f];
            float wt = Tf[r*PITCH_ + f];
            aggAcc = fmaf(m * yj * yk, wt, aggAcc);
        }
    }

    // ===== per-atom epilogue: v = ssp(agg@Wf2+bf2) @ Wd + bd; out = x + v =====
    aggs[half*128 + f] = aggAcc;
    __syncthreads();
    if (t < 128) aggs[t] = aggs[t] + aggs[128 + t];
    __syncthreads();
    if (t < 128) {
        float a1 = bf2[t];
        #pragma unroll 8
        for (int gg = 0; gg < 128; ++gg)
            a1 = fmaf(aggs[gg], Wf2[gg*NB_ + t], a1);
        t1s[t] = sspf(a1);
    }
    __syncthreads();
    if (t < 128) {
        float a2 = bd[t];
        #pragma unroll 8
        for (int gg = 0; gg < 128; ++gg)
            a2 = fmaf(t1s[gg], Wd[gg*NB_ + t], a2);
        out[atom*NB_ + t] = x[atom*NB_ + t] + a2;
    }
}

// ---------------------------------------------------------------------------
extern "C" void kernel_launch(void* const* d_in, const int* in_sizes, int n_in,
                              void* d_out, int out_size)
{
    const float* x      = (const float*)d_in[0];
    const float* triple = (const float*)d_in[1];
    const int*   nj     = (const int*)  d_in[2];
    const int*   nk     = (const int*)  d_in[3];
    const float* mask   = (const float*)d_in[4];
    const float* W1     = (const float*)d_in[5];
    const float* b1     = (const float*)d_in[6];
    const float* W2     = (const float*)d_in[7];
    const float* b2     = (const float*)d_in[8];
    const float* Win    = (const float*)d_in[9];
    const float* Wf2    = (const float*)d_in[10];
    const float* bf2    = (const float*)d_in[11];
    const float* Wd     = (const float*)d_in[12];
    const float* bd     = (const float*)d_in[13];
    float* out = (float*)d_out;

    cudaFuncSetAttribute(fused_kernel,
                         cudaFuncAttributeMaxDynamicSharedMemorySize, SMEM_BYTES);

    y_kernel<<<ATOMS_, 128>>>(x, Win);
    wconv_kernel<<<256, 128>>>(W1, W2);
    fused_kernel<<<ATOMS_, 256, SMEM_BYTES>>>(triple, nj, nk, mask,
                                              b1, b2,
                                              Wf2, bf2, Wd, bd, x, out);
}